// round 3
// baseline (speedup 1.0000x reference)
#include <cuda_runtime.h>
#include <cuda_fp16.h>
#include <cstdint>

#define SEQ 2048
#define INF 1024
#define HID 2048
#define OUT 1024
#define NCTA 128

// Scratch (device globals — allocation-free per harness rules)
__device__ float g_gx[3][(size_t)SEQ * HID];   // precomputed Wx@x_t + b, per gate
__device__ float g_h[HID];                     // current hidden state (fp32)
__device__ float g_rh[HID];                    // r * h broadcast buffer (fp32)
__device__ unsigned g_flags[2][NCTA];          // per-CTA barrier flags (epochs)

// ---------------------------------------------------------------------------
// Reset kernel: zero barrier flags and h0 each launch (graph-replay safe).
// ---------------------------------------------------------------------------
__global__ void reset_state() {
    int i = blockIdx.x * blockDim.x + threadIdx.x;
    if (i < 2 * NCTA) ((unsigned*)g_flags)[i] = 0u;
    if (i < HID) g_h[i] = 0.f;
}

// ---------------------------------------------------------------------------
// Fence-free grid barrier: per-CTA epoch flags, release-store arrive,
// acquire-vector-load poll by warp 0. Flags are monotonic within a launch.
// ---------------------------------------------------------------------------
__device__ __forceinline__ void grid_bar(unsigned* flags, unsigned epoch) {
    __syncthreads();
    if (threadIdx.x < 32) {
        if (threadIdx.x == 0) {
            asm volatile("st.release.gpu.global.b32 [%0], %1;"
                         :: "l"(flags + blockIdx.x), "r"(epoch) : "memory");
        }
        const unsigned* p = flags + (threadIdx.x << 2);   // 4 slots per lane
        for (;;) {
            unsigned a, b, c, d;
            asm volatile("ld.acquire.gpu.global.v4.b32 {%0,%1,%2,%3}, [%4];"
                         : "=r"(a), "=r"(b), "=r"(c), "=r"(d) : "l"(p));
            bool ok = (a >= epoch) & (b >= epoch) & (c >= epoch) & (d >= epoch);
            if (__all_sync(0xffffffffu, ok)) break;
        }
    }
    __syncthreads();
}

// ---------------------------------------------------------------------------
// Generic 64x64x16 fp32 tiled GEMM body (unchanged from R2):
//   C[m, n] = sum_k A[m*lda + k] * B[n*ldb + k] + bias[n]
// ---------------------------------------------------------------------------
__device__ __forceinline__ void sgemm_body(
    const float* __restrict__ A, int lda,
    const float* __restrict__ B, int ldb,
    const float* __restrict__ bias,
    float* __restrict__ C, int ldc,
    int K, int bm, int bn)
{
    __shared__ float As[16][64];
    __shared__ float Bs[16][64];

    const int tid = threadIdx.x;
    const int tx = tid & 15;
    const int ty = tid >> 4;
    const int arow = tid >> 2;
    const int ak   = (tid & 3) * 4;

    float acc[4][4];
#pragma unroll
    for (int i = 0; i < 4; ++i)
#pragma unroll
        for (int j = 0; j < 4; ++j) acc[i][j] = 0.f;

    const float* Aptr = A + (size_t)(bm + arow) * lda + ak;
    const float* Bptr = B + (size_t)(bn + arow) * ldb + ak;

    for (int k0 = 0; k0 < K; k0 += 16) {
        float4 av = *(const float4*)(Aptr + k0);
        float4 bv = *(const float4*)(Bptr + k0);
        __syncthreads();
        As[ak + 0][arow] = av.x; As[ak + 1][arow] = av.y;
        As[ak + 2][arow] = av.z; As[ak + 3][arow] = av.w;
        Bs[ak + 0][arow] = bv.x; Bs[ak + 1][arow] = bv.y;
        Bs[ak + 2][arow] = bv.z; Bs[ak + 3][arow] = bv.w;
        __syncthreads();
#pragma unroll
        for (int kk = 0; kk < 16; ++kk) {
            float4 a4 = *(const float4*)&As[kk][ty * 4];
            float4 b4 = *(const float4*)&Bs[kk][tx * 4];
            acc[0][0] = fmaf(a4.x, b4.x, acc[0][0]);
            acc[0][1] = fmaf(a4.x, b4.y, acc[0][1]);
            acc[0][2] = fmaf(a4.x, b4.z, acc[0][2]);
            acc[0][3] = fmaf(a4.x, b4.w, acc[0][3]);
            acc[1][0] = fmaf(a4.y, b4.x, acc[1][0]);
            acc[1][1] = fmaf(a4.y, b4.y, acc[1][1]);
            acc[1][2] = fmaf(a4.y, b4.z, acc[1][2]);
            acc[1][3] = fmaf(a4.y, b4.w, acc[1][3]);
            acc[2][0] = fmaf(a4.z, b4.x, acc[2][0]);
            acc[2][1] = fmaf(a4.z, b4.y, acc[2][1]);
            acc[2][2] = fmaf(a4.z, b4.z, acc[2][2]);
            acc[2][3] = fmaf(a4.z, b4.w, acc[2][3]);
            acc[3][0] = fmaf(a4.w, b4.x, acc[3][0]);
            acc[3][1] = fmaf(a4.w, b4.y, acc[3][1]);
            acc[3][2] = fmaf(a4.w, b4.z, acc[3][2]);
            acc[3][3] = fmaf(a4.w, b4.w, acc[3][3]);
        }
    }

    const int cn = bn + tx * 4;
    float4 bias4 = *(const float4*)(bias + cn);
#pragma unroll
    for (int i = 0; i < 4; ++i) {
        float4 o;
        o.x = acc[i][0] + bias4.x;
        o.y = acc[i][1] + bias4.y;
        o.z = acc[i][2] + bias4.z;
        o.w = acc[i][3] + bias4.w;
        *(float4*)(C + (size_t)(bm + ty * 4 + i) * ldc + cn) = o;
    }
}

__global__ void __launch_bounds__(256) gemm_gx(
    const float* __restrict__ X,
    const float* __restrict__ Wu, const float* __restrict__ Wr,
    const float* __restrict__ Wc,
    const float* __restrict__ bu, const float* __restrict__ br,
    const float* __restrict__ bc)
{
    const float* B;
    const float* bias;
    if (blockIdx.z == 0)      { B = Wu; bias = bu; }
    else if (blockIdx.z == 1) { B = Wr; bias = br; }
    else                      { B = Wc; bias = bc; }
    float* C = &g_gx[blockIdx.z][0];
    sgemm_body(X, INF, B + HID, HID + INF, bias, C, HID, INF,
               blockIdx.y * 64, blockIdx.x * 64);
}

__global__ void __launch_bounds__(256) gemm_y(
    const float* __restrict__ Hbuf, const float* __restrict__ Wy,
    const float* __restrict__ by, float* __restrict__ Yout)
{
    sgemm_body(Hbuf, HID, Wy, HID, by, Yout, OUT, HID,
               blockIdx.y * 64, blockIdx.x * 64);
}

// ---------------------------------------------------------------------------
// Persistent recurrent kernel. 128 CTAs x 512 threads, 1 CTA/SM.
// fp16 weights (192 KB/CTA) + fp16 h / r*h vectors in SMEM; fp32 state in L2.
//   Phase 1: u, r rows (32 slots x 16 lanes) -> publish r*h (fp32)
//   Phase 2: cand rows (16 warps)            -> h update, publish h (fp32)
// Two fence-free grid barriers per step.
// ---------------------------------------------------------------------------
#define REC_THREADS 512
// SMEM: 3*16*2048 halves (196608) + h16 (4096) + rh16 (4096) + s_u (64)
#define REC_SMEM (3 * 16 * 2048 * 2 + 2048 * 2 * 2 + 64)

__global__ void __launch_bounds__(REC_THREADS, 1) gru_rec(
    const float* __restrict__ Wu, const float* __restrict__ Wr,
    const float* __restrict__ Wc, float* __restrict__ hid_out)
{
    extern __shared__ unsigned char smem_raw[];
    __half* w_u = (__half*)smem_raw;             // [16][2048]
    __half* w_r = w_u + 16 * 2048;
    __half* w_c = w_r + 16 * 2048;
    __half* sh_h16  = w_c + 16 * 2048;           // [2048]
    __half* sh_rh16 = sh_h16 + 2048;             // [2048]
    float*  s_u     = (float*)(sh_rh16 + 2048);  // [16]

    const int cta = blockIdx.x;      // 0..127
    const int tid = threadIdx.x;     // 0..511

    // ---- Prologue: convert this CTA's weight rows to fp16 in SMEM ----
    {
        const float* src[3] = {Wu, Wr, Wc};
        __half* dst[3] = {w_u, w_r, w_c};
#pragma unroll
        for (int g = 0; g < 3; ++g) {
            const float* s = src[g];
            __half* d = dst[g];
            for (int i = tid; i < 16 * (HID / 4); i += REC_THREADS) {
                int row  = i >> 9;          // /512
                int col4 = i & 511;
                float4 v = *(const float4*)(s + (size_t)(cta * 16 + row) * (HID + INF) + col4 * 4);
                __half2 p0 = __floats2half2_rn(v.x, v.y);
                __half2 p1 = __floats2half2_rn(v.z, v.w);
                *(__half2*)(d + row * 2048 + col4 * 4)     = p0;
                *(__half2*)(d + row * 2048 + col4 * 4 + 2) = p1;
            }
        }
    }

    // h0 = 0 in fp16 mirror
    ((uint2*)sh_h16)[tid] = make_uint2(0u, 0u);   // 512 * 4 halves = 2048
    __syncthreads();

    // Phase-1 mapping: 32 slots (16 u + 16 r) x 16 lanes
    const int slot   = tid >> 4;
    const int lane16 = tid & 15;
    const int lrow   = slot & 15;
    const int rowA   = (cta << 4) + lrow;
    const bool isU   = (slot < 16);
    const uint4* wp1 = (const uint4*)((isU ? w_u : w_r) + lrow * 2048);
    const float* gx1 = isU ? &g_gx[0][0] : &g_gx[1][0];

    // Phase-2 mapping: 16 rows x 32 lanes (one warp per row)
    const int grp  = tid >> 5;
    const int l32  = tid & 31;
    const int rowC = (cta << 4) + grp;
    const uint4* wp2 = (const uint4*)(w_c + grp * 2048);
    const float* gxc = &g_gx[2][0];

    const uint4* hp16 = (const uint4*)sh_h16;
    const uint4* rp16 = (const uint4*)sh_rh16;

    for (int t = 0; t < SEQ; ++t) {
        const unsigned epoch = (unsigned)(t + 1);

        // ---- Phase 1: u, r ----
        float gxv = __ldcg(&gx1[(size_t)t * HID + rowA]);     // prefetch
        float hA  = __ldcg(&g_h[rowA]);                       // fp32 h[rowA]
        float a0 = 0.f, a1 = 0.f, a2 = 0.f, a3 = 0.f;
        float a4 = 0.f, a5 = 0.f, a6 = 0.f, a7 = 0.f;
#pragma unroll
        for (int it = 0; it < 16; ++it) {
            int k = lane16 + (it << 4);          // 0..255 (uint4 index, 8 halves)
            uint4 wv = wp1[k];
            uint4 hv = hp16[k];
            const __half2* wh = reinterpret_cast<const __half2*>(&wv);
            const __half2* hh = reinterpret_cast<const __half2*>(&hv);
            float2 w0 = __half22float2(wh[0]); float2 h0 = __half22float2(hh[0]);
            float2 w1 = __half22float2(wh[1]); float2 h1 = __half22float2(hh[1]);
            float2 w2 = __half22float2(wh[2]); float2 h2 = __half22float2(hh[2]);
            float2 w3 = __half22float2(wh[3]); float2 h3 = __half22float2(hh[3]);
            a0 = fmaf(w0.x, h0.x, a0);
            a1 = fmaf(w0.y, h0.y, a1);
            a2 = fmaf(w1.x, h1.x, a2);
            a3 = fmaf(w1.y, h1.y, a3);
            a4 = fmaf(w2.x, h2.x, a4);
            a5 = fmaf(w2.y, h2.y, a5);
            a6 = fmaf(w3.x, h3.x, a6);
            a7 = fmaf(w3.y, h3.y, a7);
        }
        float sum = ((a0 + a1) + (a2 + a3)) + ((a4 + a5) + (a6 + a7));
        sum += __shfl_down_sync(0xffffffffu, sum, 8, 16);
        sum += __shfl_down_sync(0xffffffffu, sum, 4, 16);
        sum += __shfl_down_sync(0xffffffffu, sum, 2, 16);
        sum += __shfl_down_sync(0xffffffffu, sum, 1, 16);
        if (lane16 == 0) {
            float pre = sum + gxv;
            float sg = 1.f / (1.f + __expf(-pre));
            if (isU) {
                s_u[lrow] = sg;
            } else {
                g_rh[rowA] = sg * hA;
            }
        }

        grid_bar(g_flags[0], epoch);

        // Broadcast r*h into SMEM as fp16 (512 threads x 4 values)
        {
            float4 v = __ldcg(((const float4*)g_rh) + tid);
            __half2 p0 = __floats2half2_rn(v.x, v.y);
            __half2 p1 = __floats2half2_rn(v.z, v.w);
            uint2 st;
            st.x = *(unsigned*)&p0;
            st.y = *(unsigned*)&p1;
            ((uint2*)sh_rh16)[tid] = st;
        }
        __syncthreads();

        // ---- Phase 2: candidate + h update ----
        float gxcv = __ldcg(&gxc[(size_t)t * HID + rowC]);
        float hprev = __ldcg(&g_h[rowC]);
        float c0 = 0.f, c1 = 0.f, c2 = 0.f, c3 = 0.f;
        float c4 = 0.f, c5 = 0.f, c6 = 0.f, c7 = 0.f;
#pragma unroll
        for (int it = 0; it < 8; ++it) {
            int k = l32 + (it << 5);             // 0..255
            uint4 wv = wp2[k];
            uint4 hv = rp16[k];
            const __half2* wh = reinterpret_cast<const __half2*>(&wv);
            const __half2* hh = reinterpret_cast<const __half2*>(&hv);
            float2 w0 = __half22float2(wh[0]); float2 h0 = __half22float2(hh[0]);
            float2 w1 = __half22float2(wh[1]); float2 h1 = __half22float2(hh[1]);
            float2 w2 = __half22float2(wh[2]); float2 h2 = __half22float2(hh[2]);
            float2 w3 = __half22float2(wh[3]); float2 h3 = __half22float2(hh[3]);
            c0 = fmaf(w0.x, h0.x, c0);
            c1 = fmaf(w0.y, h0.y, c1);
            c2 = fmaf(w1.x, h1.x, c2);
            c3 = fmaf(w1.y, h1.y, c3);
            c4 = fmaf(w2.x, h2.x, c4);
            c5 = fmaf(w2.y, h2.y, c5);
            c6 = fmaf(w3.x, h3.x, c6);
            c7 = fmaf(w3.y, h3.y, c7);
        }
        float sc = ((c0 + c1) + (c2 + c3)) + ((c4 + c5) + (c6 + c7));
        sc += __shfl_down_sync(0xffffffffu, sc, 16);
        sc += __shfl_down_sync(0xffffffffu, sc, 8);
        sc += __shfl_down_sync(0xffffffffu, sc, 4);
        sc += __shfl_down_sync(0xffffffffu, sc, 2);
        sc += __shfl_down_sync(0xffffffffu, sc, 1);
        if (l32 == 0) {
            float pre = sc + gxcv;
            // tanh via exp: tanh(x) = 1 - 2/(e^{2x}+1)
            float e2x = __expf(2.f * pre);
            float cand = 1.f - 2.f / (e2x + 1.f);
            float u  = s_u[grp];
            float hn = fmaf(u, cand - hprev, hprev);   // u*cand + (1-u)*h
            g_h[rowC] = hn;
            hid_out[(size_t)t * HID + rowC] = hn;
        }

        grid_bar(g_flags[1], epoch);

        // Refresh fp16 h mirror for next step
        {
            float4 v = __ldcg(((const float4*)g_h) + tid);
            __half2 p0 = __floats2half2_rn(v.x, v.y);
            __half2 p1 = __floats2half2_rn(v.z, v.w);
            uint2 st;
            st.x = *(unsigned*)&p0;
            st.y = *(unsigned*)&p1;
            ((uint2*)sh_h16)[tid] = st;
        }
        __syncthreads();
    }
}

// ---------------------------------------------------------------------------
extern "C" void kernel_launch(void* const* d_in, const int* in_sizes, int n_in,
                              void* d_out, int out_size)
{
    const float* X  = (const float*)d_in[0];
    const float* Wu = (const float*)d_in[1];
    const float* bu = (const float*)d_in[2];
    const float* Wr = (const float*)d_in[3];
    const float* br = (const float*)d_in[4];
    const float* Wc = (const float*)d_in[5];
    const float* bc = (const float*)d_in[6];
    const float* Wy = (const float*)d_in[7];
    const float* by = (const float*)d_in[8];

    float* outputs = (float*)d_out;                       // (SEQ, OUT)
    float* hidden  = (float*)d_out + (size_t)SEQ * OUT;   // (SEQ, HID)

    static bool attr_set = false;
    if (!attr_set) {
        cudaFuncSetAttribute(gru_rec, cudaFuncAttributeMaxDynamicSharedMemorySize,
                             REC_SMEM);
        attr_set = true;
    }

    // 0) Reset barrier flags + h0 (graph-replay determinism)
    reset_state<<<8, 256>>>();

    // 1) Gx_j = X @ Wx_j^T + b_j   (j = u, r, c)
    dim3 g1(HID / 64, SEQ / 64, 3);
    gemm_gx<<<g1, 256>>>(X, Wu, Wr, Wc, bu, br, bc);

    // 2) Sequential recurrence (persistent kernel, fence-free barriers)
    gru_rec<<<NCTA, REC_THREADS, REC_SMEM>>>(Wu, Wr, Wc, hidden);

    // 3) outputs = hidden @ W_y^T + b_y
    dim3 g2(OUT / 64, SEQ / 64);
    gemm_y<<<g2, 256>>>(hidden, Wy, by, outputs);
}

// round 4
// speedup vs baseline: 2.2934x; 2.2934x over previous
#include <cuda_runtime.h>
#include <cuda_fp16.h>
#include <cstdint>

#define SEQ 2048
#define INF 1024
#define HID 2048
#define OUT 1024
#define NCTA 128

// Scratch (device globals — allocation-free per harness rules)
__device__ float g_gx[3][(size_t)SEQ * HID];   // precomputed Wx@x_t + b, per gate
__device__ float g_h[HID];                     // current hidden state (fp32)
__device__ float g_rh[HID];                    // r * h broadcast buffer (fp32)
__device__ unsigned g_cnt[2];                  // monotonic barrier counts

// ---------------------------------------------------------------------------
// Reset kernel: zero barrier counts each launch (graph-replay safe).
// ---------------------------------------------------------------------------
__global__ void reset_state() {
    int i = blockIdx.x * blockDim.x + threadIdx.x;
    if (i < 2) g_cnt[i] = 0u;
}

// ---------------------------------------------------------------------------
// CG-style grid barrier pieces: RED.release arrive, single-word acquire poll.
// Monotonic epoch counts — no reset race, no MEMBAR.
// ---------------------------------------------------------------------------
__device__ __forceinline__ void arrive_cnt(unsigned* p) {
    asm volatile("red.release.gpu.global.add.u32 [%0], 1;" :: "l"(p) : "memory");
}
__device__ __forceinline__ void wait_cnt(const unsigned* p, unsigned tgt) {
    unsigned v;
    do {
        asm volatile("ld.acquire.gpu.global.u32 %0, [%1];"
                     : "=r"(v) : "l"(p) : "memory");
    } while (v < tgt);
}

// ---------------------------------------------------------------------------
// Generic 64x64x16 fp32 tiled GEMM body (unchanged):
//   C[m, n] = sum_k A[m*lda + k] * B[n*ldb + k] + bias[n]
// ---------------------------------------------------------------------------
__device__ __forceinline__ void sgemm_body(
    const float* __restrict__ A, int lda,
    const float* __restrict__ B, int ldb,
    const float* __restrict__ bias,
    float* __restrict__ C, int ldc,
    int K, int bm, int bn)
{
    __shared__ float As[16][64];
    __shared__ float Bs[16][64];

    const int tid = threadIdx.x;
    const int tx = tid & 15;
    const int ty = tid >> 4;
    const int arow = tid >> 2;
    const int ak   = (tid & 3) * 4;

    float acc[4][4];
#pragma unroll
    for (int i = 0; i < 4; ++i)
#pragma unroll
        for (int j = 0; j < 4; ++j) acc[i][j] = 0.f;

    const float* Aptr = A + (size_t)(bm + arow) * lda + ak;
    const float* Bptr = B + (size_t)(bn + arow) * ldb + ak;

    for (int k0 = 0; k0 < K; k0 += 16) {
        float4 av = *(const float4*)(Aptr + k0);
        float4 bv = *(const float4*)(Bptr + k0);
        __syncthreads();
        As[ak + 0][arow] = av.x; As[ak + 1][arow] = av.y;
        As[ak + 2][arow] = av.z; As[ak + 3][arow] = av.w;
        Bs[ak + 0][arow] = bv.x; Bs[ak + 1][arow] = bv.y;
        Bs[ak + 2][arow] = bv.z; Bs[ak + 3][arow] = bv.w;
        __syncthreads();
#pragma unroll
        for (int kk = 0; kk < 16; ++kk) {
            float4 a4 = *(const float4*)&As[kk][ty * 4];
            float4 b4 = *(const float4*)&Bs[kk][tx * 4];
            acc[0][0] = fmaf(a4.x, b4.x, acc[0][0]);
            acc[0][1] = fmaf(a4.x, b4.y, acc[0][1]);
            acc[0][2] = fmaf(a4.x, b4.z, acc[0][2]);
            acc[0][3] = fmaf(a4.x, b4.w, acc[0][3]);
            acc[1][0] = fmaf(a4.y, b4.x, acc[1][0]);
            acc[1][1] = fmaf(a4.y, b4.y, acc[1][1]);
            acc[1][2] = fmaf(a4.y, b4.z, acc[1][2]);
            acc[1][3] = fmaf(a4.y, b4.w, acc[1][3]);
            acc[2][0] = fmaf(a4.z, b4.x, acc[2][0]);
            acc[2][1] = fmaf(a4.z, b4.y, acc[2][1]);
            acc[2][2] = fmaf(a4.z, b4.z, acc[2][2]);
            acc[2][3] = fmaf(a4.z, b4.w, acc[2][3]);
            acc[3][0] = fmaf(a4.w, b4.x, acc[3][0]);
            acc[3][1] = fmaf(a4.w, b4.y, acc[3][1]);
            acc[3][2] = fmaf(a4.w, b4.z, acc[3][2]);
            acc[3][3] = fmaf(a4.w, b4.w, acc[3][3]);
        }
    }

    const int cn = bn + tx * 4;
    float4 bias4 = *(const float4*)(bias + cn);
#pragma unroll
    for (int i = 0; i < 4; ++i) {
        float4 o;
        o.x = acc[i][0] + bias4.x;
        o.y = acc[i][1] + bias4.y;
        o.z = acc[i][2] + bias4.z;
        o.w = acc[i][3] + bias4.w;
        *(float4*)(C + (size_t)(bm + ty * 4 + i) * ldc + cn) = o;
    }
}

__global__ void __launch_bounds__(256) gemm_gx(
    const float* __restrict__ X,
    const float* __restrict__ Wu, const float* __restrict__ Wr,
    const float* __restrict__ Wc,
    const float* __restrict__ bu, const float* __restrict__ br,
    const float* __restrict__ bc)
{
    const float* B;
    const float* bias;
    if (blockIdx.z == 0)      { B = Wu; bias = bu; }
    else if (blockIdx.z == 1) { B = Wr; bias = br; }
    else                      { B = Wc; bias = bc; }
    float* C = &g_gx[blockIdx.z][0];
    sgemm_body(X, INF, B + HID, HID + INF, bias, C, HID, INF,
               blockIdx.y * 64, blockIdx.x * 64);
}

__global__ void __launch_bounds__(256) gemm_y(
    const float* __restrict__ Hbuf, const float* __restrict__ Wy,
    const float* __restrict__ by, float* __restrict__ Yout)
{
    sgemm_body(Hbuf, HID, Wy, HID, by, Yout, OUT, HID,
               blockIdx.y * 64, blockIdx.x * 64);
}

// ---------------------------------------------------------------------------
// Persistent recurrent kernel. 128 CTAs x 512 threads, 1 CTA/SM.
// fp16 weights (192 KB/CTA) in SMEM; fp32 h / r*h vectors in SMEM.
// One warp per hidden row (16 rows/CTA). Per step:
//   r-dot -> publish r*h -> arrive bar1 -> u-dot (overlap) -> wait bar1
//   -> bcast r*h -> cand-dot -> h update, publish h -> arrive bar2
//   -> prefetch gx(t+1) (overlap) -> wait bar2 -> bcast h
// ---------------------------------------------------------------------------
#define REC_THREADS 512
// SMEM: 3*16*2048 halves (196608) + sh_h32 (8192) + sh_rh32 (8192)
#define REC_SMEM (3 * 16 * 2048 * 2 + 2 * 2048 * 4)

__global__ void __launch_bounds__(REC_THREADS, 1) gru_rec(
    const float* __restrict__ Wu, const float* __restrict__ Wr,
    const float* __restrict__ Wc, float* __restrict__ hid_out)
{
    extern __shared__ unsigned char smem_raw[];
    __half* w_u = (__half*)smem_raw;             // [16][2048]
    __half* w_r = w_u + 16 * 2048;
    __half* w_c = w_r + 16 * 2048;
    float* sh_h  = (float*)(w_c + 16 * 2048);    // [2048] fp32
    float* sh_rh = sh_h + 2048;                  // [2048] fp32

    const int cta = blockIdx.x;      // 0..127
    const int tid = threadIdx.x;     // 0..511

    // ---- Prologue: convert this CTA's weight rows to fp16 in SMEM ----
    {
        const float* src[3] = {Wu, Wr, Wc};
        __half* dst[3] = {w_u, w_r, w_c};
#pragma unroll
        for (int g = 0; g < 3; ++g) {
            const float* s = src[g];
            __half* d = dst[g];
            for (int i = tid; i < 16 * (HID / 4); i += REC_THREADS) {
                int row  = i >> 9;          // /512
                int col4 = i & 511;
                float4 v = *(const float4*)(s + (size_t)(cta * 16 + row) * (HID + INF) + col4 * 4);
                __half2 p0 = __floats2half2_rn(v.x, v.y);
                __half2 p1 = __floats2half2_rn(v.z, v.w);
                *(__half2*)(d + row * 2048 + col4 * 4)     = p0;
                *(__half2*)(d + row * 2048 + col4 * 4 + 2) = p1;
            }
        }
    }

    // h0 = 0 in fp32 SMEM
    ((float4*)sh_h)[tid] = make_float4(0.f, 0.f, 0.f, 0.f);
    __syncthreads();

    // One warp per row
    const int w  = tid >> 5;                 // 0..15
    const int l  = tid & 31;
    const int row = (cta << 4) + w;
    const uint4* wu_p = (const uint4*)(w_u + w * 2048);
    const uint4* wr_p = (const uint4*)(w_r + w * 2048);
    const uint4* wc_p = (const uint4*)(w_c + w * 2048);
    const float4* h4  = (const float4*)sh_h;
    const float4* rh4 = (const float4*)sh_rh;

    float h_own = 0.f;                       // lane0-valid register state
    float gxu_v = 0.f, gxr_v = 0.f, gxc_v = 0.f;
    if (l == 0) {
        gxu_v = __ldcg(&g_gx[0][row]);
        gxr_v = __ldcg(&g_gx[1][row]);
        gxc_v = __ldcg(&g_gx[2][row]);
    }

    for (int t = 0; t < SEQ; ++t) {
        const unsigned tgt = (unsigned)(t + 1) * NCTA;

        // ---- r-dot over sh_h ----
        float a0 = 0.f, a1 = 0.f, a2 = 0.f, a3 = 0.f;
        float a4 = 0.f, a5 = 0.f, a6 = 0.f, a7 = 0.f;
#pragma unroll
        for (int it = 0; it < 8; ++it) {
            int k = l + (it << 5);                   // 0..255
            uint4 wv = wr_p[k];
            float4 ha = h4[2 * k];
            float4 hb = h4[2 * k + 1];
            const __half2* wh = reinterpret_cast<const __half2*>(&wv);
            float2 f0 = __half22float2(wh[0]);
            float2 f1 = __half22float2(wh[1]);
            float2 f2 = __half22float2(wh[2]);
            float2 f3 = __half22float2(wh[3]);
            a0 = fmaf(f0.x, ha.x, a0);
            a1 = fmaf(f0.y, ha.y, a1);
            a2 = fmaf(f1.x, ha.z, a2);
            a3 = fmaf(f1.y, ha.w, a3);
            a4 = fmaf(f2.x, hb.x, a4);
            a5 = fmaf(f2.y, hb.y, a5);
            a6 = fmaf(f3.x, hb.z, a6);
            a7 = fmaf(f3.y, hb.w, a7);
        }
        float rs = ((a0 + a1) + (a2 + a3)) + ((a4 + a5) + (a6 + a7));
        rs += __shfl_down_sync(0xffffffffu, rs, 16);
        rs += __shfl_down_sync(0xffffffffu, rs, 8);
        rs += __shfl_down_sync(0xffffffffu, rs, 4);
        rs += __shfl_down_sync(0xffffffffu, rs, 2);
        rs += __shfl_down_sync(0xffffffffu, rs, 1);
        if (l == 0) {
            float r = 1.f / (1.f + __expf(-(rs + gxr_v)));
            g_rh[row] = r * h_own;
        }
        __syncthreads();
        if (tid == 0) arrive_cnt(&g_cnt[0]);

        // ---- u-dot (overlaps bar1 wake) ----
        float b0 = 0.f, b1 = 0.f, b2 = 0.f, b3 = 0.f;
        float b4 = 0.f, b5 = 0.f, b6 = 0.f, b7 = 0.f;
#pragma unroll
        for (int it = 0; it < 8; ++it) {
            int k = l + (it << 5);
            uint4 wv = wu_p[k];
            float4 ha = h4[2 * k];
            float4 hb = h4[2 * k + 1];
            const __half2* wh = reinterpret_cast<const __half2*>(&wv);
            float2 f0 = __half22float2(wh[0]);
            float2 f1 = __half22float2(wh[1]);
            float2 f2 = __half22float2(wh[2]);
            float2 f3 = __half22float2(wh[3]);
            b0 = fmaf(f0.x, ha.x, b0);
            b1 = fmaf(f0.y, ha.y, b1);
            b2 = fmaf(f1.x, ha.z, b2);
            b3 = fmaf(f1.y, ha.w, b3);
            b4 = fmaf(f2.x, hb.x, b4);
            b5 = fmaf(f2.y, hb.y, b5);
            b6 = fmaf(f3.x, hb.z, b6);
            b7 = fmaf(f3.y, hb.w, b7);
        }
        float us = ((b0 + b1) + (b2 + b3)) + ((b4 + b5) + (b6 + b7));
        us += __shfl_down_sync(0xffffffffu, us, 16);
        us += __shfl_down_sync(0xffffffffu, us, 8);
        us += __shfl_down_sync(0xffffffffu, us, 4);
        us += __shfl_down_sync(0xffffffffu, us, 2);
        us += __shfl_down_sync(0xffffffffu, us, 1);
        float u_val = 0.f;
        if (l == 0) u_val = 1.f / (1.f + __expf(-(us + gxu_v)));

        if (tid == 0) wait_cnt(&g_cnt[0], tgt);
        __syncthreads();

        // ---- broadcast r*h into SMEM (fp32) ----
        ((float4*)sh_rh)[tid] = __ldcg(((const float4*)g_rh) + tid);
        __syncthreads();

        // ---- cand-dot over sh_rh + h update ----
        float c0 = 0.f, c1 = 0.f, c2 = 0.f, c3 = 0.f;
        float c4 = 0.f, c5 = 0.f, c6 = 0.f, c7 = 0.f;
#pragma unroll
        for (int it = 0; it < 8; ++it) {
            int k = l + (it << 5);
            uint4 wv = wc_p[k];
            float4 ha = rh4[2 * k];
            float4 hb = rh4[2 * k + 1];
            const __half2* wh = reinterpret_cast<const __half2*>(&wv);
            float2 f0 = __half22float2(wh[0]);
            float2 f1 = __half22float2(wh[1]);
            float2 f2 = __half22float2(wh[2]);
            float2 f3 = __half22float2(wh[3]);
            c0 = fmaf(f0.x, ha.x, c0);
            c1 = fmaf(f0.y, ha.y, c1);
            c2 = fmaf(f1.x, ha.z, c2);
            c3 = fmaf(f1.y, ha.w, c3);
            c4 = fmaf(f2.x, hb.x, c4);
            c5 = fmaf(f2.y, hb.y, c5);
            c6 = fmaf(f3.x, hb.z, c6);
            c7 = fmaf(f3.y, hb.w, c7);
        }
        float cs = ((c0 + c1) + (c2 + c3)) + ((c4 + c5) + (c6 + c7));
        cs += __shfl_down_sync(0xffffffffu, cs, 16);
        cs += __shfl_down_sync(0xffffffffu, cs, 8);
        cs += __shfl_down_sync(0xffffffffu, cs, 4);
        cs += __shfl_down_sync(0xffffffffu, cs, 2);
        cs += __shfl_down_sync(0xffffffffu, cs, 1);
        if (l == 0) {
            float pre = cs + gxc_v;
            float e2x = __expf(2.f * pre);          // tanh(x) = 1 - 2/(e^2x + 1)
            float cand = 1.f - 2.f / (e2x + 1.f);
            float hn = fmaf(u_val, cand - h_own, h_own);
            h_own = hn;
            g_h[row] = hn;
            hid_out[(size_t)t * HID + row] = hn;
        }
        __syncthreads();
        if (tid == 0) arrive_cnt(&g_cnt[1]);

        // ---- prefetch next-step gx (overlaps bar2 wake) ----
        if (l == 0 && t + 1 < SEQ) {
            gxu_v = __ldcg(&g_gx[0][(size_t)(t + 1) * HID + row]);
            gxr_v = __ldcg(&g_gx[1][(size_t)(t + 1) * HID + row]);
            gxc_v = __ldcg(&g_gx[2][(size_t)(t + 1) * HID + row]);
        }

        if (tid == 0) wait_cnt(&g_cnt[1], tgt);
        __syncthreads();

        // ---- broadcast h into SMEM (fp32) ----
        ((float4*)sh_h)[tid] = __ldcg(((const float4*)g_h) + tid);
        __syncthreads();
    }
}

// ---------------------------------------------------------------------------
extern "C" void kernel_launch(void* const* d_in, const int* in_sizes, int n_in,
                              void* d_out, int out_size)
{
    const float* X  = (const float*)d_in[0];
    const float* Wu = (const float*)d_in[1];
    const float* bu = (const float*)d_in[2];
    const float* Wr = (const float*)d_in[3];
    const float* br = (const float*)d_in[4];
    const float* Wc = (const float*)d_in[5];
    const float* bc = (const float*)d_in[6];
    const float* Wy = (const float*)d_in[7];
    const float* by = (const float*)d_in[8];

    float* outputs = (float*)d_out;                       // (SEQ, OUT)
    float* hidden  = (float*)d_out + (size_t)SEQ * OUT;   // (SEQ, HID)

    static bool attr_set = false;
    if (!attr_set) {
        cudaFuncSetAttribute(gru_rec, cudaFuncAttributeMaxDynamicSharedMemorySize,
                             REC_SMEM);
        attr_set = true;
    }

    // 0) Reset barrier counts (graph-replay determinism)
    reset_state<<<1, 32>>>();

    // 1) Gx_j = X @ Wx_j^T + b_j   (j = u, r, c)
    dim3 g1(HID / 64, SEQ / 64, 3);
    gemm_gx<<<g1, 256>>>(X, Wu, Wr, Wc, bu, br, bc);

    // 2) Sequential recurrence (persistent kernel, RED/acquire barriers)
    gru_rec<<<NCTA, REC_THREADS, REC_SMEM>>>(Wu, Wr, Wc, hidden);

    // 3) outputs = hidden @ W_y^T + b_y
    dim3 g2(OUT / 64, SEQ / 64);
    gemm_y<<<g2, 256>>>(hidden, Wy, by, outputs);
}

// round 5
// speedup vs baseline: 2.9757x; 1.2975x over previous
#include <cuda_runtime.h>
#include <cuda_fp16.h>
#include <cstdint>

#define SEQ 2048
#define INF 1024
#define HID 2048
#define OUT 1024
#define NCTA 128

// Scratch (device globals — allocation-free per harness rules)
__device__ float  g_gx[3][(size_t)SEQ * HID];  // precomputed Wx@x_t + b, per gate
__device__ __half g_h16[HID];                  // hidden state broadcast (fp16)
__device__ __half g_rh16[HID];                 // r * h broadcast (fp16)
__device__ unsigned g_cnt[2];                  // monotonic barrier counts

// ---------------------------------------------------------------------------
// Reset kernel: zero barrier counts each launch (graph-replay safe).
// ---------------------------------------------------------------------------
__global__ void reset_state() {
    if (threadIdx.x < 2) g_cnt[threadIdx.x] = 0u;
}

// ---------------------------------------------------------------------------
// Grid barrier pieces: RED.release arrive, single-word acquire poll.
// ---------------------------------------------------------------------------
__device__ __forceinline__ void arrive_cnt(unsigned* p) {
    asm volatile("red.release.gpu.global.add.u32 [%0], 1;" :: "l"(p) : "memory");
}
__device__ __forceinline__ void wait_cnt(const unsigned* p, unsigned tgt) {
    unsigned v;
    do {
        asm volatile("ld.acquire.gpu.global.u32 %0, [%1];"
                     : "=r"(v) : "l"(p) : "memory");
    } while (v < tgt);
}

// ---------------------------------------------------------------------------
// Generic 64x64x16 fp32 tiled GEMM body (unchanged):
//   C[m, n] = sum_k A[m*lda + k] * B[n*ldb + k] + bias[n]
// ---------------------------------------------------------------------------
__device__ __forceinline__ void sgemm_body(
    const float* __restrict__ A, int lda,
    const float* __restrict__ B, int ldb,
    const float* __restrict__ bias,
    float* __restrict__ C, int ldc,
    int K, int bm, int bn)
{
    __shared__ float As[16][64];
    __shared__ float Bs[16][64];

    const int tid = threadIdx.x;
    const int tx = tid & 15;
    const int ty = tid >> 4;
    const int arow = tid >> 2;
    const int ak   = (tid & 3) * 4;

    float acc[4][4];
#pragma unroll
    for (int i = 0; i < 4; ++i)
#pragma unroll
        for (int j = 0; j < 4; ++j) acc[i][j] = 0.f;

    const float* Aptr = A + (size_t)(bm + arow) * lda + ak;
    const float* Bptr = B + (size_t)(bn + arow) * ldb + ak;

    for (int k0 = 0; k0 < K; k0 += 16) {
        float4 av = *(const float4*)(Aptr + k0);
        float4 bv = *(const float4*)(Bptr + k0);
        __syncthreads();
        As[ak + 0][arow] = av.x; As[ak + 1][arow] = av.y;
        As[ak + 2][arow] = av.z; As[ak + 3][arow] = av.w;
        Bs[ak + 0][arow] = bv.x; Bs[ak + 1][arow] = bv.y;
        Bs[ak + 2][arow] = bv.z; Bs[ak + 3][arow] = bv.w;
        __syncthreads();
#pragma unroll
        for (int kk = 0; kk < 16; ++kk) {
            float4 a4 = *(const float4*)&As[kk][ty * 4];
            float4 b4 = *(const float4*)&Bs[kk][tx * 4];
            acc[0][0] = fmaf(a4.x, b4.x, acc[0][0]);
            acc[0][1] = fmaf(a4.x, b4.y, acc[0][1]);
            acc[0][2] = fmaf(a4.x, b4.z, acc[0][2]);
            acc[0][3] = fmaf(a4.x, b4.w, acc[0][3]);
            acc[1][0] = fmaf(a4.y, b4.x, acc[1][0]);
            acc[1][1] = fmaf(a4.y, b4.y, acc[1][1]);
            acc[1][2] = fmaf(a4.y, b4.z, acc[1][2]);
            acc[1][3] = fmaf(a4.y, b4.w, acc[1][3]);
            acc[2][0] = fmaf(a4.z, b4.x, acc[2][0]);
            acc[2][1] = fmaf(a4.z, b4.y, acc[2][1]);
            acc[2][2] = fmaf(a4.z, b4.z, acc[2][2]);
            acc[2][3] = fmaf(a4.z, b4.w, acc[2][3]);
            acc[3][0] = fmaf(a4.w, b4.x, acc[3][0]);
            acc[3][1] = fmaf(a4.w, b4.y, acc[3][1]);
            acc[3][2] = fmaf(a4.w, b4.z, acc[3][2]);
            acc[3][3] = fmaf(a4.w, b4.w, acc[3][3]);
        }
    }

    const int cn = bn + tx * 4;
    float4 bias4 = *(const float4*)(bias + cn);
#pragma unroll
    for (int i = 0; i < 4; ++i) {
        float4 o;
        o.x = acc[i][0] + bias4.x;
        o.y = acc[i][1] + bias4.y;
        o.z = acc[i][2] + bias4.z;
        o.w = acc[i][3] + bias4.w;
        *(float4*)(C + (size_t)(bm + ty * 4 + i) * ldc + cn) = o;
    }
}

__global__ void __launch_bounds__(256) gemm_gx(
    const float* __restrict__ X,
    const float* __restrict__ Wu, const float* __restrict__ Wr,
    const float* __restrict__ Wc,
    const float* __restrict__ bu, const float* __restrict__ br,
    const float* __restrict__ bc)
{
    const float* B;
    const float* bias;
    if (blockIdx.z == 0)      { B = Wu; bias = bu; }
    else if (blockIdx.z == 1) { B = Wr; bias = br; }
    else                      { B = Wc; bias = bc; }
    float* C = &g_gx[blockIdx.z][0];
    sgemm_body(X, INF, B + HID, HID + INF, bias, C, HID, INF,
               blockIdx.y * 64, blockIdx.x * 64);
}

__global__ void __launch_bounds__(256) gemm_y(
    const float* __restrict__ Hbuf, const float* __restrict__ Wy,
    const float* __restrict__ by, float* __restrict__ Yout)
{
    sgemm_body(Hbuf, HID, Wy, HID, by, Yout, OUT, HID,
               blockIdx.y * 64, blockIdx.x * 64);
}

// ---------------------------------------------------------------------------
// Persistent recurrent kernel. 128 CTAs x 512 threads, 1 CTA/SM.
// fp16 weights (192 KB) + fp16 h / r*h vectors (8 KB) in SMEM.
// One warp per hidden row. Per step:
//   fused u+r dot (h read once) -> publish r*h (fp16) -> bar1
//   -> bcast r*h -> cand dot -> h update, publish h (fp16) -> bar2
//   (gx(t+1) prefetch overlaps bar2 wake) -> bcast h
// fp32 recurrence state lives in lane-0 register h_own; fp16 only in dots.
// ---------------------------------------------------------------------------
#define REC_THREADS 512
// SMEM: 3*16*2048 halves (196608) + sh_h16 (4096) + sh_rh16 (4096)
#define REC_SMEM (3 * 16 * 2048 * 2 + 2 * 2048 * 2)

__global__ void __launch_bounds__(REC_THREADS, 1) gru_rec(
    const float* __restrict__ Wu, const float* __restrict__ Wr,
    const float* __restrict__ Wc, float* __restrict__ hid_out)
{
    extern __shared__ unsigned char smem_raw[];
    __half* w_u = (__half*)smem_raw;             // [16][2048]
    __half* w_r = w_u + 16 * 2048;
    __half* w_c = w_r + 16 * 2048;
    __half* sh_h16  = w_c + 16 * 2048;           // [2048]
    __half* sh_rh16 = sh_h16 + 2048;             // [2048]

    const int cta = blockIdx.x;      // 0..127
    const int tid = threadIdx.x;     // 0..511

    // ---- Prologue: convert this CTA's weight rows to fp16 in SMEM ----
    {
        const float* src[3] = {Wu, Wr, Wc};
        __half* dst[3] = {w_u, w_r, w_c};
#pragma unroll
        for (int g = 0; g < 3; ++g) {
            const float* s = src[g];
            __half* d = dst[g];
            for (int i = tid; i < 16 * (HID / 4); i += REC_THREADS) {
                int row  = i >> 9;          // /512
                int col4 = i & 511;
                float4 v = *(const float4*)(s + (size_t)(cta * 16 + row) * (HID + INF) + col4 * 4);
                __half2 p0 = __floats2half2_rn(v.x, v.y);
                __half2 p1 = __floats2half2_rn(v.z, v.w);
                *(__half2*)(d + row * 2048 + col4 * 4)     = p0;
                *(__half2*)(d + row * 2048 + col4 * 4 + 2) = p1;
            }
        }
    }

    // h0 = 0 in fp16 SMEM mirror (512 threads x 4 halves)
    ((uint2*)sh_h16)[tid] = make_uint2(0u, 0u);
    __syncthreads();

    // One warp per row
    const int w  = tid >> 5;                 // 0..15
    const int l  = tid & 31;
    const int row = (cta << 4) + w;
    const uint4* wu_p = (const uint4*)(w_u + w * 2048);
    const uint4* wr_p = (const uint4*)(w_r + w * 2048);
    const uint4* wc_p = (const uint4*)(w_c + w * 2048);
    const uint4* hp16 = (const uint4*)sh_h16;
    const uint4* rp16 = (const uint4*)sh_rh16;

    float h_own = 0.f;                       // lane0-valid fp32 state
    float gxu_v = 0.f, gxr_v = 0.f, gxc_v = 0.f;
    if (l == 0) {
        gxu_v = __ldcg(&g_gx[0][row]);
        gxr_v = __ldcg(&g_gx[1][row]);
        gxc_v = __ldcg(&g_gx[2][row]);
    }

    for (int t = 0; t < SEQ; ++t) {
        const unsigned tgt = (unsigned)(t + 1) * NCTA;

        // ---- Fused u + r dot over sh_h16 (h read once) ----
        float ua0 = 0.f, ua1 = 0.f, ua2 = 0.f, ua3 = 0.f;
        float ra0 = 0.f, ra1 = 0.f, ra2 = 0.f, ra3 = 0.f;
#pragma unroll
        for (int it = 0; it < 8; ++it) {
            int k = l + (it << 5);                   // 0..255 uint4 (8 halves)
            uint4 wvu = wu_p[k];
            uint4 wvr = wr_p[k];
            uint4 hv  = hp16[k];
            const __half2* hu = reinterpret_cast<const __half2*>(&wvu);
            const __half2* hr = reinterpret_cast<const __half2*>(&wvr);
            const __half2* hh = reinterpret_cast<const __half2*>(&hv);
#pragma unroll
            for (int j = 0; j < 4; ++j) {
                float2 hf = __half22float2(hh[j]);
                float2 uf = __half22float2(hu[j]);
                float2 rf = __half22float2(hr[j]);
                if (j == 0 || j == 2) {
                    ua0 = fmaf(uf.x, hf.x, ua0);
                    ua1 = fmaf(uf.y, hf.y, ua1);
                    ra0 = fmaf(rf.x, hf.x, ra0);
                    ra1 = fmaf(rf.y, hf.y, ra1);
                } else {
                    ua2 = fmaf(uf.x, hf.x, ua2);
                    ua3 = fmaf(uf.y, hf.y, ua3);
                    ra2 = fmaf(rf.x, hf.x, ra2);
                    ra3 = fmaf(rf.y, hf.y, ra3);
                }
            }
        }
        float us = (ua0 + ua1) + (ua2 + ua3);
        float rs = (ra0 + ra1) + (ra2 + ra3);
#pragma unroll
        for (int o = 16; o > 0; o >>= 1) {
            us += __shfl_down_sync(0xffffffffu, us, o);
            rs += __shfl_down_sync(0xffffffffu, rs, o);
        }
        float u_val = 0.f;
        if (l == 0) {
            u_val = 1.f / (1.f + __expf(-(us + gxu_v)));
            float r = 1.f / (1.f + __expf(-(rs + gxr_v)));
            g_rh16[row] = __float2half(r * h_own);
        }
        __syncthreads();
        if (tid == 0) { arrive_cnt(&g_cnt[0]); wait_cnt(&g_cnt[0], tgt); }
        __syncthreads();

        // ---- broadcast r*h into SMEM (fp16, 4 KB) ----
        ((uint2*)sh_rh16)[tid] = __ldcg(((const uint2*)g_rh16) + tid);
        __syncthreads();

        // ---- cand dot over sh_rh16 + h update ----
        float c0 = 0.f, c1 = 0.f, c2 = 0.f, c3 = 0.f;
        float c4 = 0.f, c5 = 0.f, c6 = 0.f, c7 = 0.f;
#pragma unroll
        for (int it = 0; it < 8; ++it) {
            int k = l + (it << 5);
            uint4 wv = wc_p[k];
            uint4 hv = rp16[k];
            const __half2* wh = reinterpret_cast<const __half2*>(&wv);
            const __half2* hh = reinterpret_cast<const __half2*>(&hv);
            float2 w0 = __half22float2(wh[0]); float2 h0 = __half22float2(hh[0]);
            float2 w1 = __half22float2(wh[1]); float2 h1 = __half22float2(hh[1]);
            float2 w2 = __half22float2(wh[2]); float2 h2 = __half22float2(hh[2]);
            float2 w3 = __half22float2(wh[3]); float2 h3 = __half22float2(hh[3]);
            c0 = fmaf(w0.x, h0.x, c0);
            c1 = fmaf(w0.y, h0.y, c1);
            c2 = fmaf(w1.x, h1.x, c2);
            c3 = fmaf(w1.y, h1.y, c3);
            c4 = fmaf(w2.x, h2.x, c4);
            c5 = fmaf(w2.y, h2.y, c5);
            c6 = fmaf(w3.x, h3.x, c6);
            c7 = fmaf(w3.y, h3.y, c7);
        }
        float cs = ((c0 + c1) + (c2 + c3)) + ((c4 + c5) + (c6 + c7));
#pragma unroll
        for (int o = 16; o > 0; o >>= 1)
            cs += __shfl_down_sync(0xffffffffu, cs, o);
        if (l == 0) {
            float pre = cs + gxc_v;
            float e2x = __expf(2.f * pre);          // tanh(x) = 1 - 2/(e^2x + 1)
            float cand = 1.f - 2.f / (e2x + 1.f);
            float hn = fmaf(u_val, cand - h_own, h_own);
            h_own = hn;
            g_h16[row] = __float2half(hn);
            hid_out[(size_t)t * HID + row] = hn;    // exact fp32 output
        }
        __syncthreads();
        if (tid == 0) arrive_cnt(&g_cnt[1]);

        // ---- prefetch next-step gx (overlaps bar2 wake) ----
        if (l == 0 && t + 1 < SEQ) {
            gxu_v = __ldcg(&g_gx[0][(size_t)(t + 1) * HID + row]);
            gxr_v = __ldcg(&g_gx[1][(size_t)(t + 1) * HID + row]);
            gxc_v = __ldcg(&g_gx[2][(size_t)(t + 1) * HID + row]);
        }

        if (tid == 0) wait_cnt(&g_cnt[1], tgt);
        __syncthreads();

        // ---- broadcast h into SMEM (fp16, 4 KB) ----
        ((uint2*)sh_h16)[tid] = __ldcg(((const uint2*)g_h16) + tid);
        __syncthreads();
    }
}

// ---------------------------------------------------------------------------
extern "C" void kernel_launch(void* const* d_in, const int* in_sizes, int n_in,
                              void* d_out, int out_size)
{
    const float* X  = (const float*)d_in[0];
    const float* Wu = (const float*)d_in[1];
    const float* bu = (const float*)d_in[2];
    const float* Wr = (const float*)d_in[3];
    const float* br = (const float*)d_in[4];
    const float* Wc = (const float*)d_in[5];
    const float* bc = (const float*)d_in[6];
    const float* Wy = (const float*)d_in[7];
    const float* by = (const float*)d_in[8];

    float* outputs = (float*)d_out;                       // (SEQ, OUT)
    float* hidden  = (float*)d_out + (size_t)SEQ * OUT;   // (SEQ, HID)

    static bool attr_set = false;
    if (!attr_set) {
        cudaFuncSetAttribute(gru_rec, cudaFuncAttributeMaxDynamicSharedMemorySize,
                             REC_SMEM);
        attr_set = true;
    }

    // 0) Reset barrier counts (graph-replay determinism)
    reset_state<<<1, 32>>>();

    // 1) Gx_j = X @ Wx_j^T + b_j   (j = u, r, c)
    dim3 g1(HID / 64, SEQ / 64, 3);
    gemm_gx<<<g1, 256>>>(X, Wu, Wr, Wc, bu, br, bc);

    // 2) Sequential recurrence (persistent kernel)
    gru_rec<<<NCTA, REC_THREADS, REC_SMEM>>>(Wu, Wr, Wc, hidden);

    // 3) outputs = hidden @ W_y^T + b_y
    dim3 g2(OUT / 64, SEQ / 64);
    gemm_y<<<g2, 256>>>(hidden, Wy, by, outputs);
}

// round 7
// speedup vs baseline: 3.0639x; 1.0297x over previous
#include <cuda_runtime.h>
#include <cuda_fp16.h>
#include <cstdint>

#define SEQ 2048
#define INF 1024
#define HID 2048
#define OUT 1024
#define NCTA 128

// Scratch (device globals — allocation-free per harness rules)
__device__ float  g_gx[3][(size_t)SEQ * HID];  // precomputed Wx@x_t + b, per gate
__device__ __half g_h16[HID];                  // hidden state broadcast (fp16)
__device__ __half g_rh16[HID];                 // r * h broadcast (fp16)
__device__ unsigned g_cnt[2];                  // monotonic barrier counts

// ---------------------------------------------------------------------------
__global__ void reset_state() {
    if (threadIdx.x < 2) g_cnt[threadIdx.x] = 0u;
}

// Grid barrier pieces: RED.release arrive, single-word acquire poll.
__device__ __forceinline__ void arrive_cnt(unsigned* p) {
    asm volatile("red.release.gpu.global.add.u32 [%0], 1;" :: "l"(p) : "memory");
}
__device__ __forceinline__ void wait_cnt(const unsigned* p, unsigned tgt) {
    unsigned v;
    do {
        asm volatile("ld.acquire.gpu.global.u32 %0, [%1];"
                     : "=r"(v) : "l"(p) : "memory");
    } while (v < tgt);
}

// ---------------------------------------------------------------------------
// fp32 tiled GEMM body (unchanged): C[m,n] = sum_k A[m,k]*B[n,k] + bias[n]
// ---------------------------------------------------------------------------
__device__ __forceinline__ void sgemm_body(
    const float* __restrict__ A, int lda,
    const float* __restrict__ B, int ldb,
    const float* __restrict__ bias,
    float* __restrict__ C, int ldc,
    int K, int bm, int bn)
{
    __shared__ float As[16][64];
    __shared__ float Bs[16][64];

    const int tid = threadIdx.x;
    const int tx = tid & 15;
    const int ty = tid >> 4;
    const int arow = tid >> 2;
    const int ak   = (tid & 3) * 4;

    float acc[4][4];
#pragma unroll
    for (int i = 0; i < 4; ++i)
#pragma unroll
        for (int j = 0; j < 4; ++j) acc[i][j] = 0.f;

    const float* Aptr = A + (size_t)(bm + arow) * lda + ak;
    const float* Bptr = B + (size_t)(bn + arow) * ldb + ak;

    for (int k0 = 0; k0 < K; k0 += 16) {
        float4 av = *(const float4*)(Aptr + k0);
        float4 bv = *(const float4*)(Bptr + k0);
        __syncthreads();
        As[ak + 0][arow] = av.x; As[ak + 1][arow] = av.y;
        As[ak + 2][arow] = av.z; As[ak + 3][arow] = av.w;
        Bs[ak + 0][arow] = bv.x; Bs[ak + 1][arow] = bv.y;
        Bs[ak + 2][arow] = bv.z; Bs[ak + 3][arow] = bv.w;
        __syncthreads();
#pragma unroll
        for (int kk = 0; kk < 16; ++kk) {
            float4 a4 = *(const float4*)&As[kk][ty * 4];
            float4 b4 = *(const float4*)&Bs[kk][tx * 4];
            acc[0][0] = fmaf(a4.x, b4.x, acc[0][0]);
            acc[0][1] = fmaf(a4.x, b4.y, acc[0][1]);
            acc[0][2] = fmaf(a4.x, b4.z, acc[0][2]);
            acc[0][3] = fmaf(a4.x, b4.w, acc[0][3]);
            acc[1][0] = fmaf(a4.y, b4.x, acc[1][0]);
            acc[1][1] = fmaf(a4.y, b4.y, acc[1][1]);
            acc[1][2] = fmaf(a4.y, b4.z, acc[1][2]);
            acc[1][3] = fmaf(a4.y, b4.w, acc[1][3]);
            acc[2][0] = fmaf(a4.z, b4.x, acc[2][0]);
            acc[2][1] = fmaf(a4.z, b4.y, acc[2][1]);
            acc[2][2] = fmaf(a4.z, b4.z, acc[2][2]);
            acc[2][3] = fmaf(a4.z, b4.w, acc[2][3]);
            acc[3][0] = fmaf(a4.w, b4.x, acc[3][0]);
            acc[3][1] = fmaf(a4.w, b4.y, acc[3][1]);
            acc[3][2] = fmaf(a4.w, b4.z, acc[3][2]);
            acc[3][3] = fmaf(a4.w, b4.w, acc[3][3]);
        }
    }

    const int cn = bn + tx * 4;
    float4 bias4 = *(const float4*)(bias + cn);
#pragma unroll
    for (int i = 0; i < 4; ++i) {
        float4 o;
        o.x = acc[i][0] + bias4.x;
        o.y = acc[i][1] + bias4.y;
        o.z = acc[i][2] + bias4.z;
        o.w = acc[i][3] + bias4.w;
        *(float4*)(C + (size_t)(bm + ty * 4 + i) * ldc + cn) = o;
    }
}

__global__ void __launch_bounds__(256) gemm_gx(
    const float* __restrict__ X,
    const float* __restrict__ Wu, const float* __restrict__ Wr,
    const float* __restrict__ Wc,
    const float* __restrict__ bu, const float* __restrict__ br,
    const float* __restrict__ bc)
{
    const float* B;
    const float* bias;
    if (blockIdx.z == 0)      { B = Wu; bias = bu; }
    else if (blockIdx.z == 1) { B = Wr; bias = br; }
    else                      { B = Wc; bias = bc; }
    float* C = &g_gx[blockIdx.z][0];
    sgemm_body(X, INF, B + HID, HID + INF, bias, C, HID, INF,
               blockIdx.y * 64, blockIdx.x * 64);
}

__global__ void __launch_bounds__(256) gemm_y(
    const float* __restrict__ Hbuf, const float* __restrict__ Wy,
    const float* __restrict__ by, float* __restrict__ Yout)
{
    sgemm_body(Hbuf, HID, Wy, HID, by, Yout, OUT, HID,
               blockIdx.y * 64, blockIdx.x * 64);
}

// ---------------------------------------------------------------------------
// Tensor-core recurrent kernel. 128 CTAs x 512 threads, 1 CTA/SM.
// Weights pre-permuted into m16n8k16 A-fragment order (fp16, 192 KB SMEM).
// h / r*h vectors stored B-fragment-permuted (fp16). Per step:
//   warps 0-7:  r-gate mma (K-split 8)  -> named bar -> warp0 reduce+publish
//               -> arrive bar1 (u-warps compute during the wake)
//   warps 8-15: u-gate mma (K-split 8)
//   bcast r*h -> all 16 warps cand mma (K-split 16)
//   warp0 final reduce: u sigmoid + cand tanh + h update + publish -> bar2
// ---------------------------------------------------------------------------
#define REC_THREADS 512
// frag: 3 gates * 128 kt * 32 lanes * 16 B = 196608
// sh_h 4096 + sh_rh 4096 + part1 [2][8][16] floats = 1024 + part2 [16][16] = 1024
#define REC_SMEM (196608 + 4096 + 4096 + 1024 + 1024)

__device__ __forceinline__ void mma16816(
    float& c0, float& c1, float& c2, float& c3,
    unsigned a0, unsigned a1, unsigned a2, unsigned a3,
    unsigned b0, unsigned b1)
{
    asm volatile(
        "mma.sync.aligned.m16n8k16.row.col.f32.f16.f16.f32 "
        "{%0,%1,%2,%3}, {%4,%5,%6,%7}, {%8,%9}, {%0,%1,%2,%3};"
        : "+f"(c0), "+f"(c1), "+f"(c2), "+f"(c3)
        : "r"(a0), "r"(a1), "r"(a2), "r"(a3), "r"(b0), "r"(b1));
}

// One warp's K-slice of a 16-row matvec: NKT k-tiles starting at ktbase.
// fragBase: A-fragments for this gate; vec: B-permuted fp16 vector.
// Writes rows' partial sums (col 0) to part[row] for lanes with l%4==0.
template <int NKT>
__device__ __forceinline__ void mma_slice(
    const uint4* __restrict__ fragBase, int ktbase,
    const __half* __restrict__ vec, float* __restrict__ part, int l)
{
    float c0 = 0.f, c1 = 0.f, c2 = 0.f, c3 = 0.f;
    const int m = l & 3;
    const uint4* fp = fragBase + ktbase * 32 + l;
    const uint2* vv = (const uint2*)vec;
#pragma unroll
    for (int i = 0; i < NKT; ++i) {
        uint4 a = fp[i * 32];
        uint2 b = vv[(ktbase + i) * 4 + m];
        mma16816(c0, c1, c2, c3, a.x, a.y, a.z, a.w, b.x, b.y);
    }
    if (m == 0) {
        part[l >> 2] = c0;          // row l/4
        part[(l >> 2) + 8] = c2;    // row l/4 + 8
    }
}

__global__ void __launch_bounds__(REC_THREADS, 1) gru_rec(
    const float* __restrict__ Wu, const float* __restrict__ Wr,
    const float* __restrict__ Wc, float* __restrict__ hid_out)
{
    extern __shared__ unsigned char smem_raw[];
    uint4* fragU = (uint4*)smem_raw;                 // [128 kt][32] uint4
    uint4* fragR = fragU + 128 * 32;
    uint4* fragC = fragR + 128 * 32;
    __half* sh_h  = (__half*)(fragC + 128 * 32);     // [2048] B-permuted
    __half* sh_rh = sh_h + 2048;                     // [2048] B-permuted
    float* part1  = (float*)(sh_rh + 2048);          // [2][8][16] (u then r)
    float* part2  = part1 + 2 * 8 * 16;              // [16][16]

    const int cta = blockIdx.x;
    const int tid = threadIdx.x;
    const int wid = tid >> 5;
    const int l   = tid & 31;
    const int row0 = cta << 4;

    // ---- Prologue: permute weights into A-fragment order (fp16) ----
    // Fragment slot (gate, kt, lane): a0=(r,k2), a1=(r+8,k2), a2=(r,k2+8),
    // a3=(r+8,k2+8); r = lane/4, k2 = kt*16 + 2*(lane%4).
    {
        const float* src[3] = {Wu, Wr, Wc};
        uint4* dst[3] = {fragU, fragR, fragC};
        for (int s = tid; s < 3 * 128 * 32; s += REC_THREADS) {
            int g   = s >> 12;
            int rem = s & 4095;
            int kt  = rem >> 5;
            int ln  = rem & 31;
            int r   = ln >> 2;
            int k2  = kt * 16 + ((ln & 3) << 1);
            const float* W = src[g];
            const float* p00 = W + (size_t)(row0 + r) * (HID + INF) + k2;
            const float* p10 = W + (size_t)(row0 + r + 8) * (HID + INF) + k2;
            float2 v00 = *(const float2*)p00;        // (r,   k2..k2+1)
            float2 v10 = *(const float2*)p10;        // (r+8, k2..k2+1)
            float2 v01 = *(const float2*)(p00 + 8);  // (r,   k2+8..+9)
            float2 v11 = *(const float2*)(p10 + 8);  // (r+8, k2+8..+9)
            __half2 h00 = __floats2half2_rn(v00.x, v00.y);
            __half2 h10 = __floats2half2_rn(v10.x, v10.y);
            __half2 h01 = __floats2half2_rn(v01.x, v01.y);
            __half2 h11 = __floats2half2_rn(v11.x, v11.y);
            uint4 out;
            out.x = *(unsigned*)&h00;
            out.y = *(unsigned*)&h10;
            out.z = *(unsigned*)&h01;
            out.w = *(unsigned*)&h11;
            dst[g][kt * 32 + ln] = out;
        }
    }

    // h0 = 0 in permuted SMEM mirror
    ((uint2*)sh_h)[tid] = make_uint2(0u, 0u);
    __syncthreads();

    // warp0 lanes 0-15 carry fp32 recurrence state + gx prefetch for own row
    float h_own = 0.f;
    float gxu_v = 0.f, gxr_v = 0.f, gxc_v = 0.f;
    if (wid == 0 && l < 16) {
        gxu_v = __ldcg(&g_gx[0][row0 + l]);
        gxr_v = __ldcg(&g_gx[1][row0 + l]);
        gxc_v = __ldcg(&g_gx[2][row0 + l]);
    }

    for (int t = 0; t < SEQ; ++t) {
        const unsigned tgt = (unsigned)(t + 1) * NCTA;

        // ---- Phase 1: r (warps 0-7) overlapped with u (warps 8-15) ----
        if (wid < 8) {
            mma_slice<16>(fragR, wid * 16, sh_h, part1 + 128 + wid * 16, l);
            asm volatile("bar.sync 1, 256;" ::: "memory");   // r-warps only
            if (wid == 0) {
                if (l < 16) {
                    float rs = 0.f;
#pragma unroll
                    for (int s = 0; s < 8; ++s) rs += part1[128 + s * 16 + l];
                    float r = 1.f / (1.f + __expf(-(rs + gxr_v)));
                    g_rh16[row0 + l] = __float2half(r * h_own);
                }
                __syncwarp();
                if (l == 0) { arrive_cnt(&g_cnt[0]); wait_cnt(&g_cnt[0], tgt); }
            }
        } else {
            mma_slice<16>(fragU, (wid - 8) * 16, sh_h, part1 + (wid - 8) * 16, l);
        }
        __syncthreads();   // bar1 passed; u partials in SMEM

        // ---- broadcast r*h into B-permuted SMEM ----
        {
            int b = tid >> 2, m = tid & 3;
            unsigned u0 = __ldcg((const unsigned*)g_rh16 + (b * 8 + m));
            unsigned u1 = __ldcg((const unsigned*)g_rh16 + (b * 8 + m + 4));
            ((uint2*)sh_rh)[b * 4 + m] = make_uint2(u0, u1);
        }
        __syncthreads();

        // ---- Phase 2: cand mma, all 16 warps ----
        mma_slice<8>(fragC, wid * 8, sh_rh, part2 + wid * 16, l);
        __syncthreads();

        // ---- Final reduce: u sigmoid + cand tanh + h update ----
        if (wid == 0) {
            if (l < 16) {
                float us = 0.f, cs = 0.f;
#pragma unroll
                for (int s = 0; s < 8; ++s) us += part1[s * 16 + l];
#pragma unroll
                for (int s = 0; s < 16; ++s) cs += part2[s * 16 + l];
                float u = 1.f / (1.f + __expf(-(us + gxu_v)));
                float e2x = __expf(2.f * (cs + gxc_v));
                float cand = 1.f - 2.f / (e2x + 1.f);   // tanh
                float hn = fmaf(u, cand - h_own, h_own);
                h_own = hn;
                g_h16[row0 + l] = __float2half(hn);
                hid_out[(size_t)t * HID + row0 + l] = hn;
            }
            __syncwarp();
            if (l == 0) arrive_cnt(&g_cnt[1]);
            if (l < 16 && t + 1 < SEQ) {   // prefetch overlaps bar2 wake
                gxu_v = __ldcg(&g_gx[0][(size_t)(t + 1) * HID + row0 + l]);
                gxr_v = __ldcg(&g_gx[1][(size_t)(t + 1) * HID + row0 + l]);
                gxc_v = __ldcg(&g_gx[2][(size_t)(t + 1) * HID + row0 + l]);
            }
            if (l == 0) wait_cnt(&g_cnt[1], tgt);
        }
        __syncthreads();

        // ---- broadcast h into B-permuted SMEM ----
        {
            int b = tid >> 2, m = tid & 3;
            unsigned u0 = __ldcg((const unsigned*)g_h16 + (b * 8 + m));
            unsigned u1 = __ldcg((const unsigned*)g_h16 + (b * 8 + m + 4));
            ((uint2*)sh_h)[b * 4 + m] = make_uint2(u0, u1);
        }
        __syncthreads();
    }
}

// ---------------------------------------------------------------------------
extern "C" void kernel_launch(void* const* d_in, const int* in_sizes, int n_in,
                              void* d_out, int out_size)
{
    const float* X  = (const float*)d_in[0];
    const float* Wu = (const float*)d_in[1];
    const float* bu = (const float*)d_in[2];
    const float* Wr = (const float*)d_in[3];
    const float* br = (const float*)d_in[4];
    const float* Wc = (const float*)d_in[5];
    const float* bc = (const float*)d_in[6];
    const float* Wy = (const float*)d_in[7];
    const float* by = (const float*)d_in[8];

    float* outputs = (float*)d_out;                       // (SEQ, OUT)
    float* hidden  = (float*)d_out + (size_t)SEQ * OUT;   // (SEQ, HID)

    static bool attr_set = false;
    if (!attr_set) {
        cudaFuncSetAttribute(gru_rec, cudaFuncAttributeMaxDynamicSharedMemorySize,
                             REC_SMEM);
        attr_set = true;
    }

    // 0) Reset barrier counts (graph-replay determinism)
    reset_state<<<1, 32>>>();

    // 1) Gx_j = X @ Wx_j^T + b_j   (j = u, r, c)
    dim3 g1(HID / 64, SEQ / 64, 3);
    gemm_gx<<<g1, 256>>>(X, Wu, Wr, Wc, bu, br, bc);

    // 2) Sequential recurrence (persistent kernel, tensor-core dots)
    gru_rec<<<NCTA, REC_THREADS, REC_SMEM>>>(Wu, Wr, Wc, hidden);

    // 3) outputs = hidden @ W_y^T + b_y
    dim3 g2(OUT / 64, SEQ / 64);
    gemm_y<<<g2, 256>>>(hidden, Wy, by, outputs);
}